// round 4
// baseline (speedup 1.0000x reference)
#include <cuda_runtime.h>

#define B_  8
#define N_  512
#define F_  32
#define BN_ (B_ * N_)

// Scratch (allocation-free rule: __device__ globals)
__device__ float g_x1[BN_ * F_];
__device__ float g_xs[BN_ * F_];

// ---------------------------------------------------------------------------
// Kernel 1: x1 = relu(relu(x@Wn1+bn1)@Wn2+bn2), xs = same with Ws*.
// One warp per (b,n) row; lane = output feature. Input row broadcast via shfl.
// ---------------------------------------------------------------------------
__global__ __launch_bounds__(256)
void mlp_kernel(const float* __restrict__ x,
                const float* __restrict__ Wn1, const float* __restrict__ bn1,
                const float* __restrict__ Wn2, const float* __restrict__ bn2,
                const float* __restrict__ Ws1, const float* __restrict__ bs1,
                const float* __restrict__ Ws2, const float* __restrict__ bs2) {
    const unsigned FULL = 0xffffffffu;
    int row  = blockIdx.x * (blockDim.x >> 5) + (threadIdx.x >> 5);
    int f    = threadIdx.x & 31;
    if (row >= BN_) return;

    float xv = x[row * F_ + f];

    // n_func
    float h = bn1[f];
    #pragma unroll
    for (int k = 0; k < F_; k++)
        h = fmaf(__shfl_sync(FULL, xv, k), Wn1[k * F_ + f], h);
    h = fmaxf(h, 0.0f);

    float o = bn2[f];
    #pragma unroll
    for (int k = 0; k < F_; k++)
        o = fmaf(__shfl_sync(FULL, h, k), Wn2[k * F_ + f], o);
    g_x1[row * F_ + f] = fmaxf(o, 0.0f);

    // n_self_func
    float hs = bs1[f];
    #pragma unroll
    for (int k = 0; k < F_; k++)
        hs = fmaf(__shfl_sync(FULL, xv, k), Ws1[k * F_ + f], hs);
    hs = fmaxf(hs, 0.0f);

    float os = bs2[f];
    #pragma unroll
    for (int k = 0; k < F_; k++)
        os = fmaf(__shfl_sync(FULL, hs, k), Ws2[k * F_ + f], os);
    g_xs[row * F_ + f] = fmaxf(os, 0.0f);
}

// ---------------------------------------------------------------------------
// Kernel 2 (fused): per (b,i) block:
//   - load A[b,i,:] into SMEM, block-reduce -> inv = 1/max(rowsum, eps)
//   - stream W[b,i,:,:] once: copy to out AND accumulate a_j * w * x1[b,j,f]
//   - x2[b,i,f] = inv * acc[f] + xs[b,i,f]
// float4 lane mapping per warp iteration: lane covers (j = jb + lane>>3,
// feature-quad fq = lane&7) -> contiguous 512B load/store per warp.
// ---------------------------------------------------------------------------
__global__ __launch_bounds__(256, 4)
void agg_kernel(const float* __restrict__ A, const float* __restrict__ W,
                float* __restrict__ outW, float* __restrict__ outX2) {
    const unsigned FULL = 0xffffffffu;
    int bi   = blockIdx.x;        // b*N + i
    int b    = bi >> 9;           // N_ = 512
    int tid  = threadIdx.x;
    int warp = tid >> 5;
    int lane = tid & 31;

    __shared__ float sA[N_];
    __shared__ float sws[8];
    __shared__ float sacc[8][F_];

    // ---- A row load + L1-norm reduce ----
    const float* Arow = A + (size_t)bi * N_;
    float local = 0.0f;
    #pragma unroll
    for (int j = tid; j < N_; j += 256) {
        float a = Arow[j];
        sA[j] = a;
        local += a;               // A is 0/1, |A| == A
    }
    #pragma unroll
    for (int o = 16; o; o >>= 1)
        local += __shfl_xor_sync(FULL, local, o);
    if (lane == 0) sws[warp] = local;
    __syncthreads();
    float rowsum = sws[0] + sws[1] + sws[2] + sws[3]
                 + sws[4] + sws[5] + sws[6] + sws[7];
    float inv = 1.0f / fmaxf(rowsum, 1e-12f);

    // ---- fused stream: W copy + edge-weighted aggregation ----
    const float4* Wp  = (const float4*)(W    + (size_t)bi * N_ * F_);
    float4*       Op  = (float4*)      (outW + (size_t)bi * N_ * F_);
    const float4* x1p = (const float4*)(g_x1 + (size_t)b  * N_ * F_);

    int fq = lane & 7;            // which float4 of the 32-feature row
    int jo = lane >> 3;           // 0..3: j offset within the 4-j warp tile
    float4 acc = make_float4(0.0f, 0.0f, 0.0f, 0.0f);

    #pragma unroll 4
    for (int jb = warp * 4; jb < N_; jb += 32) {
        int idx = jb * 8 + lane;              // contiguous float4 per warp
        float4 w = __ldcs(Wp + idx);          // streaming read (no reuse)
        __stcs(Op + idx, w);                  // streaming copy-out
        int j = jb + jo;
        float a = sA[j];
        float4 xv = x1p[j * 8 + fq];          // L1/L2 resident (64KB/batch)
        acc.x = fmaf(a * w.x, xv.x, acc.x);
        acc.y = fmaf(a * w.y, xv.y, acc.y);
        acc.z = fmaf(a * w.z, xv.z, acc.z);
        acc.w = fmaf(a * w.w, xv.w, acc.w);
    }

    // reduce across the 4 lanes sharing the same feature-quad (xor 8, 16)
    #pragma unroll
    for (int o = 8; o <= 16; o <<= 1) {
        acc.x += __shfl_xor_sync(FULL, acc.x, o);
        acc.y += __shfl_xor_sync(FULL, acc.y, o);
        acc.z += __shfl_xor_sync(FULL, acc.z, o);
        acc.w += __shfl_xor_sync(FULL, acc.w, o);
    }
    if (lane < 8) {
        sacc[warp][lane * 4 + 0] = acc.x;
        sacc[warp][lane * 4 + 1] = acc.y;
        sacc[warp][lane * 4 + 2] = acc.z;
        sacc[warp][lane * 4 + 3] = acc.w;
    }
    __syncthreads();

    // cross-warp reduce + epilogue: x2 = inv*acc + xs
    if (tid < F_) {
        float s = 0.0f;
        #pragma unroll
        for (int w8 = 0; w8 < 8; w8++) s += sacc[w8][tid];
        outX2[(size_t)bi * F_ + tid] = fmaf(s, inv, g_xs[(size_t)bi * F_ + tid]);
    }
}

// ---------------------------------------------------------------------------
// Launch. Inputs (metadata order): A, W, x, Wn1, bn1, Wn2, bn2, Ws1, bs1,
// Ws2, bs2. Output: [W (B*N*N*F) | x2 (B*N*F)] as float32.
// ---------------------------------------------------------------------------
extern "C" void kernel_launch(void* const* d_in, const int* in_sizes, int n_in,
                              void* d_out, int out_size) {
    const float* A   = (const float*)d_in[0];
    const float* W   = (const float*)d_in[1];
    const float* x   = (const float*)d_in[2];
    const float* Wn1 = (const float*)d_in[3];
    const float* bn1 = (const float*)d_in[4];
    const float* Wn2 = (const float*)d_in[5];
    const float* bn2 = (const float*)d_in[6];
    const float* Ws1 = (const float*)d_in[7];
    const float* bs1 = (const float*)d_in[8];
    const float* Ws2 = (const float*)d_in[9];
    const float* bs2 = (const float*)d_in[10];

    float* out   = (float*)d_out;
    float* outW  = out;
    float* outX2 = out + (size_t)B_ * N_ * N_ * F_;

    // 8 rows per 256-thread block
    mlp_kernel<<<BN_ / 8, 256>>>(x, Wn1, bn1, Wn2, bn2, Ws1, bs1, Ws2, bs2);
    agg_kernel<<<BN_, 256>>>(A, W, outW, outX2);
}

// round 5
// speedup vs baseline: 1.0574x; 1.0574x over previous
#include <cuda_runtime.h>

#define B_  8
#define N_  512
#define F_  32
#define BN_ (B_ * N_)

// Scratch (allocation-free rule: __device__ globals)
__device__ float g_x1[BN_ * F_];
__device__ float g_inv[BN_];

// ---------------------------------------------------------------------------
// Prep kernel: one warp per (b,n) row.
//  - g_inv[row] = 1 / max(sum_j A[row,j], eps)   (A is 0/1 -> |A| == A)
//  - g_x1 = relu(relu(x@Wn1+bn1)@Wn2+bn2)
//  - outX2 = relu(relu(x@Ws1+bs1)@Ws2+bs2)       (self path; agg adds onto it)
// lane = feature index; input row broadcast via shfl. Weights are L1-resident.
// ---------------------------------------------------------------------------
__global__ __launch_bounds__(256)
void prep_kernel(const float* __restrict__ x, const float* __restrict__ A,
                 const float* __restrict__ Wn1, const float* __restrict__ bn1,
                 const float* __restrict__ Wn2, const float* __restrict__ bn2,
                 const float* __restrict__ Ws1, const float* __restrict__ bs1,
                 const float* __restrict__ Ws2, const float* __restrict__ bs2,
                 float* __restrict__ outX2) {
    const unsigned FULL = 0xffffffffu;
    int row = blockIdx.x * (blockDim.x >> 5) + (threadIdx.x >> 5);
    int f   = threadIdx.x & 31;
    if (row >= BN_) return;

    // ---- L1-norm of A row (512 floats = 128 float4, 4 per lane) ----
    const float4* A4 = (const float4*)(A + (size_t)row * N_);
    float s = 0.0f;
    #pragma unroll
    for (int k = 0; k < 4; k++) {
        float4 a = A4[f + k * 32];
        s += (a.x + a.y) + (a.z + a.w);
    }
    #pragma unroll
    for (int o = 16; o; o >>= 1) s += __shfl_xor_sync(FULL, s, o);
    if (f == 0) g_inv[row] = 1.0f / fmaxf(s, 1e-12f);

    float xv = x[row * F_ + f];

    // ---- n_func -> g_x1 ----
    float h = bn1[f];
    #pragma unroll
    for (int k = 0; k < F_; k++)
        h = fmaf(__shfl_sync(FULL, xv, k), Wn1[k * F_ + f], h);
    h = fmaxf(h, 0.0f);
    float o1 = bn2[f];
    #pragma unroll
    for (int k = 0; k < F_; k++)
        o1 = fmaf(__shfl_sync(FULL, h, k), Wn2[k * F_ + f], o1);
    g_x1[row * F_ + f] = fmaxf(o1, 0.0f);

    // ---- n_self_func -> outX2 (base value; agg atomically adds) ----
    float hs = bs1[f];
    #pragma unroll
    for (int k = 0; k < F_; k++)
        hs = fmaf(__shfl_sync(FULL, xv, k), Ws1[k * F_ + f], hs);
    hs = fmaxf(hs, 0.0f);
    float o2 = bs2[f];
    #pragma unroll
    for (int k = 0; k < F_; k++)
        o2 = fmaf(__shfl_sync(FULL, hs, k), Ws2[k * F_ + f], o2);
    outX2[row * F_ + f] = fmaxf(o2, 0.0f);
}

// ---------------------------------------------------------------------------
// Aggregation + W copy: barrier-free, SMEM-free streaming.
// One warp = one (bi, chunk) tile, chunk = 128 consecutive j's (16 KB of W).
// Lane map per iteration: jo = lane>>3 (4 j's), fq = lane&7 (feature quad)
//   -> one contiguous 512 B float4 load/store per warp per iteration.
// Partial sum reduced across jo lanes, scaled by g_inv[bi], atomicAdd'ed
// into outX2 (max 4 writers per element, L2-resident 512 KB target).
// ---------------------------------------------------------------------------
__global__ __launch_bounds__(256)
void agg_kernel(const float* __restrict__ A, const float* __restrict__ W,
                float* __restrict__ outW, float* __restrict__ outX2) {
    const unsigned FULL = 0xffffffffu;
    int gw   = blockIdx.x * (blockDim.x >> 5) + (threadIdx.x >> 5); // 0..16383
    int lane = threadIdx.x & 31;
    int bi   = gw >> 2;           // row  (b*N + i)
    int c    = gw & 3;            // 128-j chunk within the row
    int b    = bi >> 9;           // N_ = 512
    int fq   = lane & 7;
    int jo   = lane >> 3;

    const float4* Wp   = (const float4*)(W    + (size_t)bi * N_ * F_) + c * (128 * 8);
    float4*       Op   = (float4*)      (outW + (size_t)bi * N_ * F_) + c * (128 * 8);
    const float4* x1p  = (const float4*)(g_x1 + (size_t)b  * N_ * F_) + c * (128 * 8);
    const float*  Arow = A + (size_t)bi * N_ + c * 128;

    float4 acc = make_float4(0.0f, 0.0f, 0.0f, 0.0f);

    #pragma unroll 4
    for (int jb = 0; jb < 128; jb += 4) {
        int idx  = jb * 8 + lane;             // contiguous 512B per warp
        float4 w = __ldcs(Wp + idx);          // streaming read (no reuse)
        __stcs(Op + idx, w);                  // streaming copy-out
        float  a  = __ldg(Arow + jb + jo);    // 8-lane broadcast, L1/L2 hot
        float4 xv = x1p[(jb + jo) * 8 + fq];  // x1 row, L1/L2 resident
        acc.x = fmaf(a * w.x, xv.x, acc.x);
        acc.y = fmaf(a * w.y, xv.y, acc.y);
        acc.z = fmaf(a * w.z, xv.z, acc.z);
        acc.w = fmaf(a * w.w, xv.w, acc.w);
    }

    // reduce across the 4 lanes sharing a feature-quad (xor 8, 16)
    #pragma unroll
    for (int o = 8; o <= 16; o <<= 1) {
        acc.x += __shfl_xor_sync(FULL, acc.x, o);
        acc.y += __shfl_xor_sync(FULL, acc.y, o);
        acc.z += __shfl_xor_sync(FULL, acc.z, o);
        acc.w += __shfl_xor_sync(FULL, acc.w, o);
    }

    if (lane < 8) {
        float inv  = g_inv[bi];
        float* dst = outX2 + (size_t)bi * F_ + lane * 4;
        atomicAdd(dst + 0, acc.x * inv);
        atomicAdd(dst + 1, acc.y * inv);
        atomicAdd(dst + 2, acc.z * inv);
        atomicAdd(dst + 3, acc.w * inv);
    }
}

// ---------------------------------------------------------------------------
// Launch. Inputs (metadata order): A, W, x, Wn1, bn1, Wn2, bn2, Ws1, bs1,
// Ws2, bs2. Output: [W (B*N*N*F) | x2 (B*N*F)] as float32.
// ---------------------------------------------------------------------------
extern "C" void kernel_launch(void* const* d_in, const int* in_sizes, int n_in,
                              void* d_out, int out_size) {
    const float* A   = (const float*)d_in[0];
    const float* W   = (const float*)d_in[1];
    const float* x   = (const float*)d_in[2];
    const float* Wn1 = (const float*)d_in[3];
    const float* bn1 = (const float*)d_in[4];
    const float* Wn2 = (const float*)d_in[5];
    const float* bn2 = (const float*)d_in[6];
    const float* Ws1 = (const float*)d_in[7];
    const float* bs1 = (const float*)d_in[8];
    const float* Ws2 = (const float*)d_in[9];
    const float* bs2 = (const float*)d_in[10];

    float* out   = (float*)d_out;
    float* outW  = out;
    float* outX2 = out + (size_t)B_ * N_ * N_ * F_;

    // 8 warps (rows) per block
    prep_kernel<<<BN_ / 8, 256>>>(x, A, Wn1, bn1, Wn2, bn2,
                                  Ws1, bs1, Ws2, bs2, outX2);
    // 16K independent warp-tiles: 4 chunks per row, 8 warps per block
    agg_kernel<<<(BN_ * 4) / 8, 256>>>(A, W, outW, outX2);
}